// round 9
// baseline (speedup 1.0000x reference)
#include <cuda_runtime.h>
#include <math.h>

#define NUM_ITEMS  10000
#define NUM_USERS  10000
#define NUM_GROUPS 5000
#define EMB_DIM    64
#define BATCH      16384

#define WCAP 1024             // per-warp hit-index buffer (4 KB)

// Scratch (allocation-free rule: __device__ globals)
__device__ float g_user_embeds[NUM_USERS * EMB_DIM];   // 2.56 MB
__device__ float g_group_embeds[NUM_GROUPS * EMB_DIM]; // 1.28 MB

// ---------------------------------------------------------------------------
// Paired gather: half-warp h (lanes 0-15 / 16-31) loads embedding row
// idx[j+2t+h] as float4 (lane covers cols 4*li..4*li+3). One warp-instruction
// fetches TWO 256B rows. Batches of 8 pairs (16 indices), double-buffered so
// only one L2 latency is exposed per flush.
// ---------------------------------------------------------------------------
__device__ __forceinline__ void load_pair_batch(const int* __restrict__ idxbuf,
                                                int j, int nh, int h, int li,
                                                const float4* __restrict__ emb4,
                                                float4* e)
{
    #pragma unroll
    for (int t = 0; t < 8; ++t) {
        const int jj = j + 2 * t + h;
        const bool valid = (jj < nh);
        const int id = valid ? idxbuf[jj] : 0;
        if (valid) e[t] = emb4[id * 16 + li];
        else       e[t] = make_float4(0.f, 0.f, 0.f, 0.f);
    }
}

__device__ __forceinline__ void gather_accumulate(const int* __restrict__ idxbuf,
                                                  int nh, int h, int li,
                                                  const float4* __restrict__ emb4,
                                                  float4& acc)
{
    if (nh <= 0) return;
    float4 ea[8];
    load_pair_batch(idxbuf, 0, nh, h, li, emb4, ea);
    for (int j = 16; j < nh; j += 16) {
        float4 eb[8];
        load_pair_batch(idxbuf, j, nh, h, li, emb4, eb);   // in flight while...
        #pragma unroll
        for (int t = 0; t < 8; ++t) {
            acc.x += ea[t].x; acc.y += ea[t].y;
            acc.z += ea[t].z; acc.w += ea[t].w;
        }
        #pragma unroll
        for (int t = 0; t < 8; ++t) ea[t] = eb[t];
    }
    #pragma unroll
    for (int t = 0; t < 8; ++t) {
        acc.x += ea[t].x; acc.y += ea[t].y;
        acc.z += ea[t].z; acc.w += ea[t].w;
    }
}

// ---------------------------------------------------------------------------
// One warp per full row. Stream scan (8x LDG.128 __ldcs prefetch, byte-pack
// PRMT detection, REDUX total, smem-atomic slot alloc), deferred paired gather.
// Matrix entries are exactly {0.0f, 1.0f}: byte3 == 0x3F iff hit; divisor
// count equals the number of hits.
// ---------------------------------------------------------------------------
template <int NCOLS, bool CLAMP>
__global__ __launch_bounds__(256)
void row_aggregate_kernel(const float* __restrict__ mat,
                          const float* __restrict__ emb,
                          float* __restrict__ out,
                          int nrows)
{
    __shared__ int s_idx[8][WCAP];                // 32 KB
    __shared__ int s_nh[8];

    const int lane = threadIdx.x & 31;
    const int wl   = threadIdx.x >> 5;
    const int row  = blockIdx.x * 8 + wl;
    if (row >= nrows) return;

    const int h  = lane >> 4;                     // half-warp id
    const int li = lane & 15;                     // lane within half

    int* idxbuf = s_idx[wl];
    const float4* __restrict__ emb4 = (const float4*)emb;
    const int ncols4 = NCOLS / 4;                 // 2500
    const float4* __restrict__ row4 = (const float4*)(mat + (size_t)row * NCOLS);

    float4 acc = make_float4(0.f, 0.f, 0.f, 0.f);
    int tot = 0, nh = 0;
    if (lane == 0) s_nh[wl] = 0;
    __syncwarp();

    for (int base = 0; base < ncols4; base += 256) {
        // ---- prefetch 8 independent float4 streaming loads (MLP=8) ----
        float4 v[8];
        #pragma unroll
        for (int u = 0; u < 8; ++u) {
            const int jj = base + u * 32 + lane;
            v[u] = (jj < ncols4) ? __ldcs(&row4[jj])
                                 : make_float4(0.f, 0.f, 0.f, 0.f);
        }

        // ---- byte-pack detection: br[u] bit 8c set iff element c hit ----
        unsigned br[8];
        unsigned ucnt = 0u;
        #pragma unroll
        for (int u = 0; u < 8; ++u) {
            const unsigned x = __float_as_uint(v[u].x);
            const unsigned y = __float_as_uint(v[u].y);
            const unsigned z = __float_as_uint(v[u].z);
            const unsigned w = __float_as_uint(v[u].w);
            const unsigned p = __byte_perm(x, y, 0x0073) |
                               __byte_perm(z, w, 0x7300);
            br[u] = p & 0x01010101u;
            ucnt = __dp4a(br[u], 0x01010101u, ucnt);
        }
        const int cnt = (int)ucnt;

        // ---- block total + flush check ----
        const int btot = __reduce_add_sync(0xffffffffu, cnt);
        if (nh + btot > WCAP) {
            __syncwarp();
            gather_accumulate(idxbuf, nh, h, li, emb4, acc);
            tot += nh; nh = 0;
            if (lane == 0) s_nh[wl] = 0;
            __syncwarp();
        }

        // ---- slot allocation via smem atomic (order-free) ----
        int off = atomicAdd(&s_nh[wl], cnt);
        const int ebase = base * 4 + lane * 4;
        #pragma unroll
        for (int u = 0; u < 8; ++u) {
            unsigned b = br[u];
            while (b) {
                const int k = __ffs(b) - 1;           // bit 8c
                b &= b - 1;
                idxbuf[off++] = ebase + u * 128 + (k >> 3);
            }
        }
        nh += btot;
        __syncwarp();
    }

    // ---- row-end gather (typically the only one) ----
    __syncwarp();
    gather_accumulate(idxbuf, nh, h, li, emb4, acc);
    tot += nh;

    // ---- combine halves, normalize, write (lanes 0-15: 16B each) ----
    acc.x += __shfl_xor_sync(0xffffffffu, acc.x, 16);
    acc.y += __shfl_xor_sync(0xffffffffu, acc.y, 16);
    acc.z += __shfl_xor_sync(0xffffffffu, acc.z, 16);
    acc.w += __shfl_xor_sync(0xffffffffu, acc.w, 16);

    float div = (float)tot;
    if (CLAMP) div = fmaxf(div, 1.0f);
    const float inv = 1.0f / div;

    if (h == 0) {
        float4* __restrict__ out4 = (float4*)(out + (size_t)row * EMB_DIM);
        out4[li] = make_float4(acc.x * inv, acc.y * inv,
                               acc.z * inv, acc.w * inv);
    }
}

// ---------------------------------------------------------------------------
// MLP: y = sigmoid(relu([ge[g], ie[it]] @ W1 + b1) @ W2 + b2)
// ---------------------------------------------------------------------------
__global__ void mlp_kernel(const float* __restrict__ group_embeds,
                           const float* __restrict__ item_emb,
                           const float* __restrict__ W1,  // [128, 8]
                           const float* __restrict__ b1,  // [8]
                           const float* __restrict__ W2,  // [8, 1]
                           const float* __restrict__ b2,  // [1]
                           const int*   __restrict__ gidx,
                           const int*   __restrict__ iidx,
                           float* __restrict__ out,
                           int batch)
{
    __shared__ float sW1[2 * EMB_DIM * 8];
    __shared__ float sb1[8];
    __shared__ float sW2[8];
    __shared__ float sb2;

    for (int i = threadIdx.x; i < 2 * EMB_DIM * 8; i += blockDim.x)
        sW1[i] = W1[i];
    if (threadIdx.x < 8) {
        sb1[threadIdx.x] = b1[threadIdx.x];
        sW2[threadIdx.x] = W2[threadIdx.x];
    }
    if (threadIdx.x == 0) sb2 = b2[0];
    __syncthreads();

    const int i = blockIdx.x * blockDim.x + threadIdx.x;
    if (i >= batch) return;

    const int g  = gidx[i];
    const int it = iidx[i];
    const float2* __restrict__ ge2 =
        (const float2*)(group_embeds + (size_t)g * EMB_DIM);
    const float2* __restrict__ ie2 =
        (const float2*)(item_emb + (size_t)it * EMB_DIM);

    float h[8];
    #pragma unroll
    for (int k = 0; k < 8; ++k) h[k] = sb1[k];

    #pragma unroll 4
    for (int d2 = 0; d2 < 32; ++d2) {
        const float2 e = ge2[d2];
        const int d0 = 2 * d2;
        #pragma unroll
        for (int k = 0; k < 8; ++k) {
            h[k] += e.x * sW1[(d0    ) * 8 + k];
            h[k] += e.y * sW1[(d0 + 1) * 8 + k];
        }
    }
    #pragma unroll 4
    for (int d2 = 0; d2 < 32; ++d2) {
        const float2 e = ie2[d2];
        const int d0 = 2 * d2 + EMB_DIM;
        #pragma unroll
        for (int k = 0; k < 8; ++k) {
            h[k] += e.x * sW1[(d0    ) * 8 + k];
            h[k] += e.y * sW1[(d0 + 1) * 8 + k];
        }
    }

    float y = sb2;
    #pragma unroll
    for (int k = 0; k < 8; ++k)
        y += fmaxf(h[k], 0.0f) * sW2[k];

    out[i] = 1.0f / (1.0f + expf(-y));
}

// ---------------------------------------------------------------------------
extern "C" void kernel_launch(void* const* d_in, const int* in_sizes, int n_in,
                              void* d_out, int out_size)
{
    const float* item_emb = (const float*)d_in[0];
    const float* ui       = (const float*)d_in[1];
    const float* gu       = (const float*)d_in[2];
    const float* W1       = (const float*)d_in[3];
    const float* b1       = (const float*)d_in[4];
    const float* W2       = (const float*)d_in[5];
    const float* b2       = (const float*)d_in[6];
    const int*   gidx     = (const int*)d_in[7];
    const int*   iidx     = (const int*)d_in[8];
    float* out            = (float*)d_out;

    float* user_embeds;
    float* group_embeds;
    cudaGetSymbolAddress((void**)&user_embeds,  g_user_embeds);
    cudaGetSymbolAddress((void**)&group_embeds, g_group_embeds);

    // Kernel 1: user_embeds = (ui @ item_emb) / clamp(count, 1)
    // 1250 blocks x 8 warps = 10000 warps = one full row each.
    row_aggregate_kernel<NUM_ITEMS, true>
        <<<1250, 256>>>(ui, item_emb, user_embeds, NUM_USERS);

    // Kernel 2: group_embeds = (gu @ user_embeds) / count  (raw, no clamp)
    // 625 blocks x 8 warps = 5000 warps = one full row each.
    row_aggregate_kernel<NUM_USERS, false>
        <<<625, 256>>>(gu, user_embeds, group_embeds, NUM_GROUPS);

    // Kernel 3: MLP head
    {
        const int threads = 128;
        const int grid = (BATCH + threads - 1) / threads;
        mlp_kernel<<<grid, threads>>>(group_embeds, item_emb,
                                      W1, b1, W2, b2, gidx, iidx,
                                      out, BATCH);
    }
}

// round 10
// speedup vs baseline: 1.1626x; 1.1626x over previous
#include <cuda_runtime.h>
#include <math.h>

#define NUM_ITEMS  10000
#define NUM_USERS  10000
#define NUM_GROUPS 5000
#define EMB_DIM    64
#define BATCH      16384

#define WCAP   512            // per-warp hit-index buffer; >= max hits per 2KB block
#define BLKF4  128            // float4 per stream block (2 KB)

// Scratch (allocation-free rule: __device__ globals)
__device__ float g_user_embeds[NUM_USERS * EMB_DIM];   // 2.56 MB
__device__ float g_group_embeds[NUM_GROUPS * EMB_DIM]; // 1.28 MB

// ---- cp.async helpers -----------------------------------------------------
__device__ __forceinline__ void cp_async16(void* smem, const void* gmem) {
    unsigned saddr = (unsigned)__cvta_generic_to_shared(smem);
    asm volatile("cp.async.cg.shared.global [%0], [%1], 16;"
                 :: "r"(saddr), "l"(gmem));
}
#define CP_COMMIT()  asm volatile("cp.async.commit_group;" ::: "memory")
#define CP_WAIT(n)   asm volatile("cp.async.wait_group %0;" :: "n"(n) : "memory")

// ---------------------------------------------------------------------------
// Batched gather (R8 form): indices in smem, 8 independent LDG.64 in flight,
// double-buffered so one L2 latency is exposed per flush.
// ---------------------------------------------------------------------------
__device__ __forceinline__ void load_batch(const int* __restrict__ idxbuf, int j,
                                           int lane, const float2* __restrict__ emb2,
                                           float2* e)
{
    int id[8];
    #pragma unroll
    for (int t = 0; t < 8; ++t) id[t] = idxbuf[j + t];           // LDS broadcast
    #pragma unroll
    for (int t = 0; t < 8; ++t) e[t] = emb2[id[t] * 32 + lane];  // 8 indep LDG.64
}

__device__ __forceinline__ void gather_accumulate(const int* __restrict__ idxbuf,
                                                  int nh, int lane,
                                                  const float2* __restrict__ emb2,
                                                  float2& acc)
{
    const int nfull = nh & ~7;
    if (nfull) {
        float2 ea[8];
        load_batch(idxbuf, 0, lane, emb2, ea);
        for (int j = 8; j < nfull; j += 8) {
            float2 eb[8];
            load_batch(idxbuf, j, lane, emb2, eb);       // in flight while...
            #pragma unroll
            for (int t = 0; t < 8; ++t) { acc.x += ea[t].x; acc.y += ea[t].y; }
            #pragma unroll
            for (int t = 0; t < 8; ++t) ea[t] = eb[t];
        }
        #pragma unroll
        for (int t = 0; t < 8; ++t) { acc.x += ea[t].x; acc.y += ea[t].y; }
    }
    for (int j = nfull; j < nh; ++j) {
        const float2 e = emb2[idxbuf[j] * 32 + lane];
        acc.x += e.x; acc.y += e.y;
    }
}

// ---------------------------------------------------------------------------
// One warp per full row. Stream via cp.async.cg into a double-buffered smem
// stage (copies stay in flight across ALL processing, register-free); byte-pack
// PRMT detection; REDUX total; smem-atomic slot alloc; deferred batched gather.
// Each lane reads back exactly the bytes it copied -> wait_group is the only
// synchronization the stage needs.
// Matrix entries are exactly {0.0f, 1.0f}: byte3 == 0x3F iff hit; divisor
// count equals number of hits.
// ---------------------------------------------------------------------------
template <int NCOLS, bool CLAMP>
__global__ __launch_bounds__(128)
void row_aggregate_kernel(const float* __restrict__ mat,
                          const float* __restrict__ emb,
                          float* __restrict__ out,
                          int nrows)
{
    __shared__ float4 s_stage[4][2][BLKF4];       // 16 KB
    __shared__ int    s_idx[4][WCAP];             // 8 KB
    __shared__ int    s_nh[4];

    const int lane = threadIdx.x & 31;
    const int wl   = threadIdx.x >> 5;
    const int row  = blockIdx.x * 4 + wl;
    if (row >= nrows) return;

    const int ncols4 = NCOLS / 4;                 // 2500
    const int nblk   = (ncols4 + BLKF4 - 1) / BLKF4;
    const float4* __restrict__ row4 = (const float4*)(mat + (size_t)row * NCOLS);
    const float2* __restrict__ emb2 = (const float2*)emb;
    int* idxbuf = s_idx[wl];

    float2 acc = make_float2(0.f, 0.f);
    int nh = 0, tot = 0;
    if (lane == 0) s_nh[wl] = 0;
    __syncwarp();

    // ---- prologue: stage block 0 ----
    {
        #pragma unroll
        for (int u = 0; u < 4; ++u) {
            const int jj = u * 32 + lane;
            if (jj < ncols4) cp_async16(&s_stage[wl][0][u * 32 + lane], &row4[jj]);
        }
        CP_COMMIT();
    }

    for (int b = 0; b < nblk; ++b) {
        // ---- issue block b+1 (stays in flight through all processing) ----
        if (b + 1 < nblk) {
            const int nb = (b + 1) * BLKF4;
            #pragma unroll
            for (int u = 0; u < 4; ++u) {
                const int jj = nb + u * 32 + lane;
                if (jj < ncols4)
                    cp_async16(&s_stage[wl][(b + 1) & 1][u * 32 + lane], &row4[jj]);
            }
        }
        CP_COMMIT();
        CP_WAIT(1);                               // block b's copies complete

        // ---- detect on block b from smem ----
        const int base = b * BLKF4;
        const float4* stage = s_stage[wl][b & 1];
        unsigned br[4];
        unsigned ucnt = 0u;
        #pragma unroll
        for (int u = 0; u < 4; ++u) {
            const int jj = base + u * 32 + lane;
            float4 v = (jj < ncols4) ? stage[u * 32 + lane]
                                     : make_float4(0.f, 0.f, 0.f, 0.f);
            const unsigned x = __float_as_uint(v.x);
            const unsigned y = __float_as_uint(v.y);
            const unsigned z = __float_as_uint(v.z);
            const unsigned w = __float_as_uint(v.w);
            const unsigned p = __byte_perm(x, y, 0x0073) |
                               __byte_perm(z, w, 0x7300);
            br[u] = p & 0x01010101u;
            ucnt = __dp4a(br[u], 0x01010101u, ucnt);
        }
        const int cnt = (int)ucnt;

        // ---- total + flush check (flush overlaps next block's copy) ----
        const int btot = __reduce_add_sync(0xffffffffu, cnt);
        if (nh + btot > WCAP) {
            __syncwarp();
            gather_accumulate(idxbuf, nh, lane, emb2, acc);
            tot += nh; nh = 0;
            if (lane == 0) s_nh[wl] = 0;
            __syncwarp();
        }

        // ---- slot allocation via smem atomic (order-free) ----
        int off = atomicAdd(&s_nh[wl], cnt);
        const int ebase = base * 4 + lane * 4;
        #pragma unroll
        for (int u = 0; u < 4; ++u) {
            unsigned bm = br[u];
            while (bm) {
                const int k = __ffs(bm) - 1;      // bit 8c
                bm &= bm - 1;
                idxbuf[off++] = ebase + u * 128 + (k >> 3);
            }
        }
        nh += btot;
        __syncwarp();
    }
    CP_WAIT(0);

    // ---- row-end gather (typically the only one) ----
    gather_accumulate(idxbuf, nh, lane, emb2, acc);
    tot += nh;

    float div = (float)tot;
    if (CLAMP) div = fmaxf(div, 1.0f);
    const float inv = 1.0f / div;

    float2* __restrict__ out2 = (float2*)(out + (size_t)row * EMB_DIM);
    out2[lane] = make_float2(acc.x * inv, acc.y * inv);
}

// ---------------------------------------------------------------------------
// MLP: y = sigmoid(relu([ge[g], ie[it]] @ W1 + b1) @ W2 + b2)
// ---------------------------------------------------------------------------
__global__ void mlp_kernel(const float* __restrict__ group_embeds,
                           const float* __restrict__ item_emb,
                           const float* __restrict__ W1,  // [128, 8]
                           const float* __restrict__ b1,  // [8]
                           const float* __restrict__ W2,  // [8, 1]
                           const float* __restrict__ b2,  // [1]
                           const int*   __restrict__ gidx,
                           const int*   __restrict__ iidx,
                           float* __restrict__ out,
                           int batch)
{
    __shared__ float sW1[2 * EMB_DIM * 8];
    __shared__ float sb1[8];
    __shared__ float sW2[8];
    __shared__ float sb2;

    for (int i = threadIdx.x; i < 2 * EMB_DIM * 8; i += blockDim.x)
        sW1[i] = W1[i];
    if (threadIdx.x < 8) {
        sb1[threadIdx.x] = b1[threadIdx.x];
        sW2[threadIdx.x] = W2[threadIdx.x];
    }
    if (threadIdx.x == 0) sb2 = b2[0];
    __syncthreads();

    const int i = blockIdx.x * blockDim.x + threadIdx.x;
    if (i >= batch) return;

    const int g  = gidx[i];
    const int it = iidx[i];
    const float2* __restrict__ ge2 =
        (const float2*)(group_embeds + (size_t)g * EMB_DIM);
    const float2* __restrict__ ie2 =
        (const float2*)(item_emb + (size_t)it * EMB_DIM);

    float h[8];
    #pragma unroll
    for (int k = 0; k < 8; ++k) h[k] = sb1[k];

    #pragma unroll 4
    for (int d2 = 0; d2 < 32; ++d2) {
        const float2 e = ge2[d2];
        const int d0 = 2 * d2;
        #pragma unroll
        for (int k = 0; k < 8; ++k) {
            h[k] += e.x * sW1[(d0    ) * 8 + k];
            h[k] += e.y * sW1[(d0 + 1) * 8 + k];
        }
    }
    #pragma unroll 4
    for (int d2 = 0; d2 < 32; ++d2) {
        const float2 e = ie2[d2];
        const int d0 = 2 * d2 + EMB_DIM;
        #pragma unroll
        for (int k = 0; k < 8; ++k) {
            h[k] += e.x * sW1[(d0    ) * 8 + k];
            h[k] += e.y * sW1[(d0 + 1) * 8 + k];
        }
    }

    float y = sb2;
    #pragma unroll
    for (int k = 0; k < 8; ++k)
        y += fmaxf(h[k], 0.0f) * sW2[k];

    out[i] = 1.0f / (1.0f + expf(-y));
}

// ---------------------------------------------------------------------------
extern "C" void kernel_launch(void* const* d_in, const int* in_sizes, int n_in,
                              void* d_out, int out_size)
{
    const float* item_emb = (const float*)d_in[0];
    const float* ui       = (const float*)d_in[1];
    const float* gu       = (const float*)d_in[2];
    const float* W1       = (const float*)d_in[3];
    const float* b1       = (const float*)d_in[4];
    const float* W2       = (const float*)d_in[5];
    const float* b2       = (const float*)d_in[6];
    const int*   gidx     = (const int*)d_in[7];
    const int*   iidx     = (const int*)d_in[8];
    float* out            = (float*)d_out;

    float* user_embeds;
    float* group_embeds;
    cudaGetSymbolAddress((void**)&user_embeds,  g_user_embeds);
    cudaGetSymbolAddress((void**)&group_embeds, g_group_embeds);

    // Kernel 1: user_embeds = (ui @ item_emb) / clamp(count, 1)
    // 2500 blocks x 4 warps = 10000 warps = one full row each.
    row_aggregate_kernel<NUM_ITEMS, true>
        <<<2500, 128>>>(ui, item_emb, user_embeds, NUM_USERS);

    // Kernel 2: group_embeds = (gu @ user_embeds) / count  (raw, no clamp)
    // 1250 blocks x 4 warps = 5000 warps = one full row each.
    row_aggregate_kernel<NUM_USERS, false>
        <<<1250, 128>>>(gu, user_embeds, group_embeds, NUM_GROUPS);

    // Kernel 3: MLP head
    {
        const int threads = 128;
        const int grid = (BATCH + threads - 1) / threads;
        mlp_kernel<<<grid, threads>>>(group_embeds, item_emb,
                                      W1, b1, W2, b2, gidx, iidx,
                                      out, BATCH);
    }
}